// round 6
// baseline (speedup 1.0000x reference)
#include <cuda_runtime.h>
#include <math.h>
#include <stdint.h>

// Problem dims
#define TT   512
#define DD   256
#define HH   256
#define H2   512

#define NCHUNK 16
#define LCH    32

// K1: 256 blocks = 16 chunks x 16 groups of 16 channels, 256 threads
#define NTH1 256

// smem layout K1 (floats)
#define STRA 260                        // padded k-major row stride
#define AS_OFF 0                        // as[32][260]  (x tile, 32 t rows)
#define BS_OFF (32 * STRA)              // bs[32][260]  (16 B1 rows + 16 B2 rows)
#define P_OFF  (BS_OFF + 32 * STRA)     // P[2][32][33] GEMM half partials
#define P_TS   33
#define P_HS   (32 * P_TS)
#define ES_OFF (P_OFF + 2 * P_HS)       // Es[16][32] subchunk ends
#define SMEM_FLOATS (ES_OFF + 16 * 32)
#define SMEM_BYTES (SMEM_FLOATS * 4)    // ~77 KB -> 2 blocks/SM

__device__ float g_E[NCHUNK * H2];      // per-chunk end states

#define FMA2(acc, a, b) \
    asm("fma.rn.f32x2 %0, %1, %2, %0;" : "+l"(acc) : "l"(a), "l"(b))

__device__ __forceinline__ float f32x2_sum(unsigned long long v) {
    float lo, hi;
    asm("mov.b64 {%0, %1}, %2;" : "=f"(lo), "=f"(hi) : "l"(v));
    return lo + hi;
}

__device__ __forceinline__ void cp16(float* smem_dst, const void* gsrc) {
    uint32_t sa = (uint32_t)__cvta_generic_to_shared(smem_dst);
    asm volatile("cp.async.cg.shared.global [%0], [%1], 16;" :: "r"(sa), "l"(gsrc));
}
#define CP_COMMIT() asm volatile("cp.async.commit_group;" ::: "memory")
#define CP_WAIT0()  asm volatile("cp.async.wait_group 0;" ::: "memory")
#define BARN(id, n) asm volatile("bar.sync %0, %1;" :: "r"(id), "r"(n) : "memory")

__device__ __forceinline__ void cmul(float a, float b, float& p1, float& p2) {
    float n1 = a * p1 - b * p2;
    float n2 = fmaf(a, p2, b * p1);
    p1 = n1; p2 = n2;
}

__device__ __forceinline__ void coeffs(const float* __restrict__ lamda,
                                       const float* __restrict__ theta,
                                       int h, float& c, float& s, float& gam)
{
    float e = expf(lamda[h]);
    float y = expf(-e);
    float z = expf(theta[h]);
    gam = sqrtf(fmaxf(1.0f - y * y, 0.0f));
    float cz, sz;
    sincosf(z, &sz, &cz);
    c = y * cz;
    s = y * sz;
}

// ---------------------------------------------------------------------------
// K1: block (j = chunk, g = 16-channel group). 256 threads, 2 blocks/SM.
//  staging (k-halves) -> GEMM 32t x 32c x 256k -> parallel scan -> store local
//  results to out, chunk ends to g_E. No grid barrier.
// ---------------------------------------------------------------------------
__global__ __launch_bounds__(NTH1, 2) void rtrl_main(
    const float* __restrict__ x,
    const float* __restrict__ B1,
    const float* __restrict__ B2,
    const float* __restrict__ lamda,
    const float* __restrict__ theta,
    float* __restrict__ out)
{
    extern __shared__ float sm[];
    float* as = sm + AS_OFF;
    float* bs = sm + BS_OFF;
    float* P  = sm + P_OFF;
    float* Es = sm + ES_OFF;

    const int j   = blockIdx.x;          // chunk
    const int g   = blockIdx.y;          // 16-channel group
    const int t0  = j * LCH;
    const int ch0 = g * 16;
    const int tid = threadIdx.x;

    // ---- per-half staging: half hf loads k-quads [32*hf, 32*hf+32) ----
    const int hf = tid >> 7;             // 0/1
    const int r  = tid & 127;
    const float4* x4 = (const float4*)x;
#pragma unroll
    for (int i = 0; i < 8; i++) {        // as: 32 rows x 32 quads
        int idx = i * 128 + r;
        int row = idx >> 5;
        int qd  = 32 * hf + (idx & 31);
        cp16(&as[row * STRA + 4 * qd], &x4[(t0 + row) * 64 + qd]);
    }
#pragma unroll
    for (int i = 0; i < 8; i++) {        // bs: 32 rows (16 B1 + 16 B2) x 32 quads
        int idx = i * 128 + r;
        int row = idx >> 5;
        int qd  = 32 * hf + (idx & 31);
        const float4* Bsrc = (row < 16)
            ? (const float4*)(B1 + (ch0 + row) * DD)
            : (const float4*)(B2 + (ch0 + row - 16) * DD);
        cp16(&bs[row * STRA + 4 * qd], Bsrc + qd);
    }
    CP_COMMIT();

    // per-channel coefficients (16 channels; use ch = tid & 15)
    const int ch = tid & 15;
    const int sc = tid >> 4;             // 0..15 subchunk of 2 steps
    const int h  = ch0 + ch;
    float cc, ss_, gam;
    coeffs(lamda, theta, h, cc, ss_, gam);
    float a2 = cc, b2 = ss_; cmul(cc, ss_, a2, b2);          // R^2

    CP_WAIT0();
    BARN(1 + hf, 128);                   // half-local: own strip resident

    // ---- GEMM half: 32t x 32c x 128k, micro 4x2, f32x2 accumulators ----
    const int tsub = r >> 4;             // rows {tsub+8i}, i<4
    const int csub = r & 15;             // cols {csub+16i}, i<2

    unsigned long long acc[4][2];
#pragma unroll
    for (int i = 0; i < 4; i++) { acc[i][0] = 0ull; acc[i][1] = 0ull; }

#pragma unroll 8
    for (int kq = 32 * hf; kq < 32 * hf + 32; kq++) {
        int kf = kq * 4;
        ulonglong2 av[4], bv[2];
#pragma unroll
        for (int i = 0; i < 4; i++)
            av[i] = *(const ulonglong2*)&as[(tsub + 8 * i) * STRA + kf];
#pragma unroll
        for (int i = 0; i < 2; i++)
            bv[i] = *(const ulonglong2*)&bs[(csub + 16 * i) * STRA + kf];
#pragma unroll
        for (int i = 0; i < 4; i++)
#pragma unroll
            for (int jb = 0; jb < 2; jb++) {
                FMA2(acc[i][jb], av[i].x, bv[jb].x);
                FMA2(acc[i][jb], av[i].y, bv[jb].y);
            }
    }

#pragma unroll
    for (int i = 0; i < 4; i++)
#pragma unroll
        for (int jb = 0; jb < 2; jb++)
            P[hf * P_HS + (tsub + 8 * i) * P_TS + csub + 16 * jb] = f32x2_sum(acc[i][jb]);
    __syncthreads();

    // ---- parallel in-chunk scan: 16 subchunks of 2 steps, 16 channels ----
    float rl1[2], rl2[2];
    {
        float l1 = 0.f, l2 = 0.f;
#pragma unroll
        for (int i = 0; i < 2; i++) {
            int tt = 2 * sc + i;
            float b1v = P[tt * P_TS + ch]      + P[P_HS + tt * P_TS + ch];
            float b2v = P[tt * P_TS + 16 + ch] + P[P_HS + tt * P_TS + 16 + ch];
            float n1 = fmaf(cc, l1, fmaf(-ss_, l2, gam * b1v));
            float n2 = fmaf(cc, l2, fmaf( ss_, l1, gam * b2v));
            l1 = n1; l2 = n2;
            rl1[i] = l1; rl2[i] = l2;
        }
        Es[sc * 32 + ch]      = l1;
        Es[sc * 32 + 16 + ch] = l2;
    }
    __syncthreads();

    // subchunk carry: start(sc) = sum_{u<sc} R2^(sc-1-u) Es[u]
    {
        float p1 = 0.f, p2 = 0.f;
#pragma unroll
        for (int u = 0; u < 15; u++) {
            if (u < sc) {
                float e1 = Es[u * 32 + ch];
                float e2 = Es[u * 32 + 16 + ch];
                float n1 = fmaf(a2, p1, fmaf(-b2, p2, e1));
                float n2 = fmaf(a2, p2, fmaf( b2, p1, e2));
                p1 = n1; p2 = n2;
            }
        }
#pragma unroll
        for (int i = 0; i < 2; i++) {
            float n1 = fmaf(cc, p1, -ss_ * p2);
            float n2 = fmaf(cc, p2,  ss_ * p1);
            p1 = n1; p2 = n2;
            rl1[i] += p1; rl2[i] += p2;
        }
    }
    if (sc == 15) {
        g_E[j * H2 + h]      = rl1[1];
        g_E[j * H2 + HH + h] = rl2[1];
    }

    // ---- store chunk-local results (corrected within chunk) ----
#pragma unroll
    for (int i = 0; i < 2; i++) {
        int tt = 2 * sc + i;
        out[(t0 + tt) * H2 + h]      = rl1[i];
        out[(t0 + tt) * H2 + HH + h] = rl2[i];
    }
}

// ---------------------------------------------------------------------------
// K2: block (j = 1..15, gg = 32-channel group), 512 threads.
// carry = sum_{i<j} R^{32(j-1-i)} g_E[i]; out += rotated carry.
// ---------------------------------------------------------------------------
__global__ __launch_bounds__(512) void rtrl_fix(
    const float* __restrict__ lamda,
    const float* __restrict__ theta,
    float* __restrict__ out)
{
    const int j   = blockIdx.x + 1;
    const int gg  = blockIdx.y;          // 0..7
    const int tid = threadIdx.x;
    const int ch  = tid & 31;
    const int sc  = tid >> 5;            // 0..15
    const int h   = gg * 32 + ch;
    const int t0  = j * LCH;

    float cc, ss_, gam;
    coeffs(lamda, theta, h, cc, ss_, gam);
    (void)gam;
    float a2 = cc, b2 = ss_;    cmul(cc,  ss_, a2, b2);      // R^2
    float a4 = a2, b4 = b2;     cmul(a2,  b2,  a4, b4);      // R^4
    float a8 = a4, b8 = b4;     cmul(a4,  b4,  a8, b8);      // R^8
    float a16 = a8, b16 = b8;   cmul(a8,  b8,  a16, b16);    // R^16
    float a32 = a16, b32 = b16; cmul(a16, b16, a32, b32);    // R^32

    // cross-chunk carry (fully unrolled, predicated -> batched loads)
    float p1 = 0.f, p2 = 0.f;
#pragma unroll
    for (int i = 0; i < NCHUNK - 1; i++) {
        if (i < j) {
            float e1 = __ldcg(&g_E[i * H2 + h]);
            float e2 = __ldcg(&g_E[i * H2 + HH + h]);
            float n1 = fmaf(a32, p1, fmaf(-b32, p2, e1));
            float n2 = fmaf(a32, p2, fmaf( b32, p1, e2));
            p1 = n1; p2 = n2;
        }
    }
    // rotate carry to subchunk start: p *= R2^sc (binary exponent)
    if (sc & 1) cmul(a2,  b2,  p1, p2);
    if (sc & 2) cmul(a4,  b4,  p1, p2);
    if (sc & 4) cmul(a8,  b8,  p1, p2);
    if (sc & 8) cmul(a16, b16, p1, p2);

#pragma unroll
    for (int i = 0; i < 2; i++) {
        float n1 = fmaf(cc, p1, -ss_ * p2);
        float n2 = fmaf(cc, p2,  ss_ * p1);
        p1 = n1; p2 = n2;
        int tt = 2 * sc + i;
        out[(t0 + tt) * H2 + h]      += p1;
        out[(t0 + tt) * H2 + HH + h] += p2;
    }
}

// ---------------------------------------------------------------------------
extern "C" void kernel_launch(void* const* d_in, const int* in_sizes, int n_in,
                              void* d_out, int out_size)
{
    const float* x     = (const float*)d_in[0];
    const float* lamda = (const float*)d_in[1];
    const float* theta = (const float*)d_in[2];
    const float* B1    = (const float*)d_in[3];
    const float* B2    = (const float*)d_in[4];
    float* out = (float*)d_out;

    static bool attr_set = false;
    if (!attr_set) {
        cudaFuncSetAttribute(rtrl_main,
                             cudaFuncAttributeMaxDynamicSharedMemorySize,
                             SMEM_BYTES);
        attr_set = true;
    }

    dim3 grid1(NCHUNK, HH / 16);         // (16, 16) = 256 blocks, 2/SM
    rtrl_main<<<grid1, NTH1, SMEM_BYTES>>>(x, B1, B2, lamda, theta, out);
    dim3 grid2(NCHUNK - 1, HH / 32);     // (15, 8) = 120 blocks
    rtrl_fix<<<grid2, 512>>>(lamda, theta, out);
}

// round 7
// speedup vs baseline: 1.1358x; 1.1358x over previous
#include <cuda_runtime.h>
#include <math.h>
#include <stdint.h>

// Problem dims
#define TT   512
#define DD   256
#define HH   256
#define H2   512

#define NCHUNK 16
#define LCH    32
#define NBLK   256                      // 16 chunks x 16 channel-groups
#define NTHR   256

// smem layout (floats)
#define STRA 260                        // padded k-major row stride
#define AS_OFF 0                        // as[32][260]  x tile (32 t rows)
#define BS_OFF (32 * STRA)              // bs[32][260]  16 B1 rows + 16 B2 rows
#define P_OFF  (BS_OFF + 32 * STRA)     // P[2][32][33] GEMM half partials
#define P_TS   33
#define P_HS   (32 * P_TS)
#define ES_OFF (P_OFF + 2 * P_HS)       // Es[16][32] subchunk ends
#define SMEM_FLOATS (ES_OFF + 16 * 32)
#define SMEM_BYTES (SMEM_FLOATS * 4)    // ~77 KB -> 2 blocks/SM

__device__ float g_E[NCHUNK * H2];      // per-chunk end states
__device__ int   g_ctr = 0;             // monotonic barrier counter (replay-safe)

#define FMA2(acc, a, b) \
    asm("fma.rn.f32x2 %0, %1, %2, %0;" : "+l"(acc) : "l"(a), "l"(b))

__device__ __forceinline__ float f32x2_sum(unsigned long long v) {
    float lo, hi;
    asm("mov.b64 {%0, %1}, %2;" : "=f"(lo), "=f"(hi) : "l"(v));
    return lo + hi;
}

__device__ __forceinline__ void cp16(float* smem_dst, const void* gsrc) {
    uint32_t sa = (uint32_t)__cvta_generic_to_shared(smem_dst);
    asm volatile("cp.async.cg.shared.global [%0], [%1], 16;" :: "r"(sa), "l"(gsrc));
}
#define CP_COMMIT() asm volatile("cp.async.commit_group;" ::: "memory")
#define CP_WAIT0()  asm volatile("cp.async.wait_group 0;" ::: "memory")
#define BARN(id, n) asm volatile("bar.sync %0, %1;" :: "r"(id), "r"(n) : "memory")

__device__ __forceinline__ void cmul(float a, float b, float& p1, float& p2) {
    float n1 = a * p1 - b * p2;
    float n2 = fmaf(a, p2, b * p1);
    p1 = n1; p2 = n2;
}

__device__ __forceinline__ void coeffs(const float* __restrict__ lamda,
                                       const float* __restrict__ theta,
                                       int h, float& c, float& s, float& gam)
{
    float e = expf(lamda[h]);
    float y = expf(-e);
    float z = expf(theta[h]);
    gam = sqrtf(fmaxf(1.0f - y * y, 0.0f));
    float cz, sz;
    sincosf(z, &sz, &cz);
    c = y * cz;
    s = y * sz;
}

// ---------------------------------------------------------------------------
// Single persistent kernel, 256 blocks, 2 blocks/SM (desynced phases).
// Block (j = chunk, g = 16-channel group):
//   staging (k-halves, named barriers) -> GEMM 32t x 32c x 256k (f32x2)
//   -> parallel scan 16x2 -> g_E -> grid barrier -> carry -> single store.
// ---------------------------------------------------------------------------
__global__ __launch_bounds__(NTHR, 2) void rtrl_kernel(
    const float* __restrict__ x,
    const float* __restrict__ B1,
    const float* __restrict__ B2,
    const float* __restrict__ lamda,
    const float* __restrict__ theta,
    float* __restrict__ out)
{
    extern __shared__ float sm[];
    float* as = sm + AS_OFF;
    float* bs = sm + BS_OFF;
    float* P  = sm + P_OFF;
    float* Es = sm + ES_OFF;

    const int j   = blockIdx.x;          // chunk
    const int g   = blockIdx.y;          // 16-channel group
    const int t0  = j * LCH;
    const int ch0 = g * 16;
    const int tid = threadIdx.x;

    // ---- per-half staging: half hf loads k-quads [32*hf, 32*hf+32) ----
    const int hf = tid >> 7;             // 0/1
    const int r  = tid & 127;
    const float4* x4 = (const float4*)x;
#pragma unroll
    for (int i = 0; i < 8; i++) {        // as: 32 rows x 32 quads
        int idx = i * 128 + r;
        int row = idx >> 5;
        int qd  = 32 * hf + (idx & 31);
        cp16(&as[row * STRA + 4 * qd], &x4[(t0 + row) * 64 + qd]);
    }
#pragma unroll
    for (int i = 0; i < 8; i++) {        // bs: 32 rows (16 B1 + 16 B2) x 32 quads
        int idx = i * 128 + r;
        int row = idx >> 5;
        int qd  = 32 * hf + (idx & 31);
        const float4* Bsrc = (row < 16)
            ? (const float4*)(B1 + (ch0 + row) * DD)
            : (const float4*)(B2 + (ch0 + row - 16) * DD);
        cp16(&bs[row * STRA + 4 * qd], Bsrc + qd);
    }
    CP_COMMIT();

    // per-channel coefficients + rotation powers (overlap staging latency)
    const int ch = tid & 15;
    const int sc = tid >> 4;             // 0..15 subchunk of 2 steps
    const int h  = ch0 + ch;
    float cc, ss_, gam;
    coeffs(lamda, theta, h, cc, ss_, gam);
    float a2 = cc, b2 = ss_;    cmul(cc,  ss_, a2, b2);      // R^2
    float a4 = a2, b4 = b2;     cmul(a2,  b2,  a4, b4);      // R^4
    float a8 = a4, b8 = b4;     cmul(a4,  b4,  a8, b8);      // R^8
    float a16 = a8, b16 = b8;   cmul(a8,  b8,  a16, b16);    // R^16
    float a32 = a16, b32 = b16; cmul(a16, b16, a32, b32);    // R^32

    CP_WAIT0();
    BARN(1 + hf, 128);                   // half-local: own strip resident

    // ---- GEMM half: 32t x 32c x 128k, micro 4x2, f32x2 accumulators ----
    const int tsub = r >> 4;             // rows {tsub+8i}, i<4
    const int csub = r & 15;             // cols {csub+16i}, i<2

    unsigned long long acc[4][2];
#pragma unroll
    for (int i = 0; i < 4; i++) { acc[i][0] = 0ull; acc[i][1] = 0ull; }

#pragma unroll 8
    for (int kq = 32 * hf; kq < 32 * hf + 32; kq++) {
        int kf = kq * 4;
        ulonglong2 av[4], bv[2];
#pragma unroll
        for (int i = 0; i < 4; i++)
            av[i] = *(const ulonglong2*)&as[(tsub + 8 * i) * STRA + kf];
#pragma unroll
        for (int i = 0; i < 2; i++)
            bv[i] = *(const ulonglong2*)&bs[(csub + 16 * i) * STRA + kf];
#pragma unroll
        for (int i = 0; i < 4; i++)
#pragma unroll
            for (int jb = 0; jb < 2; jb++) {
                FMA2(acc[i][jb], av[i].x, bv[jb].x);
                FMA2(acc[i][jb], av[i].y, bv[jb].y);
            }
    }

#pragma unroll
    for (int i = 0; i < 4; i++)
#pragma unroll
        for (int jb = 0; jb < 2; jb++)
            P[hf * P_HS + (tsub + 8 * i) * P_TS + csub + 16 * jb] = f32x2_sum(acc[i][jb]);
    __syncthreads();

    // ---- parallel in-chunk scan: 16 subchunks of 2 steps, 16 channels ----
    float rl1[2], rl2[2];
    {
        float l1 = 0.f, l2 = 0.f;
#pragma unroll
        for (int i = 0; i < 2; i++) {
            int tt = 2 * sc + i;
            float b1v = P[tt * P_TS + ch]      + P[P_HS + tt * P_TS + ch];
            float b2v = P[tt * P_TS + 16 + ch] + P[P_HS + tt * P_TS + 16 + ch];
            float n1 = fmaf(cc, l1, fmaf(-ss_, l2, gam * b1v));
            float n2 = fmaf(cc, l2, fmaf( ss_, l1, gam * b2v));
            l1 = n1; l2 = n2;
            rl1[i] = l1; rl2[i] = l2;
        }
        Es[sc * 32 + ch]      = l1;
        Es[sc * 32 + 16 + ch] = l2;
    }
    __syncthreads();

    // subchunk carry: start(sc) = sum_{u<sc} R2^(sc-1-u) Es[u]
    {
        float p1 = 0.f, p2 = 0.f;
#pragma unroll
        for (int u = 0; u < 15; u++) {
            if (u < sc) {
                float e1 = Es[u * 32 + ch];
                float e2 = Es[u * 32 + 16 + ch];
                float n1 = fmaf(a2, p1, fmaf(-b2, p2, e1));
                float n2 = fmaf(a2, p2, fmaf( b2, p1, e2));
                p1 = n1; p2 = n2;
            }
        }
#pragma unroll
        for (int i = 0; i < 2; i++) {
            float n1 = fmaf(cc, p1, -ss_ * p2);
            float n2 = fmaf(cc, p2,  ss_ * p1);
            p1 = n1; p2 = n2;
            rl1[i] += p1; rl2[i] += p2;
        }
    }
    // chunk end state (tt = 31) -> g_E, fenced by the writing threads
    if (sc == 15) {
        g_E[j * H2 + h]      = rl1[1];
        g_E[j * H2 + HH + h] = rl2[1];
        __threadfence();
    }
    __syncthreads();

    // ---- software grid barrier (256 blocks, all co-resident at 2/SM) ----
    if (tid == 0) {
        __threadfence();
        int ticket = atomicAdd(&g_ctr, 1);
        int target = ((ticket >> 8) + 1) << 8;   // multiples of 256
        while (*((volatile int*)&g_ctr) < target) { }
        __threadfence();
    }
    __syncthreads();

    // ---- cross-chunk carry (fully unrolled, predicated -> batched loads) ----
    float p1 = 0.f, p2 = 0.f;
#pragma unroll
    for (int i = 0; i < NCHUNK - 1; i++) {
        if (i < j) {
            float e1 = __ldcg(&g_E[i * H2 + h]);
            float e2 = __ldcg(&g_E[i * H2 + HH + h]);
            float n1 = fmaf(a32, p1, fmaf(-b32, p2, e1));
            float n2 = fmaf(a32, p2, fmaf( b32, p1, e2));
            p1 = n1; p2 = n2;
        }
    }
    // rotate carry to subchunk start: p *= R2^sc (binary exponent)
    if (sc & 1) cmul(a2,  b2,  p1, p2);
    if (sc & 2) cmul(a4,  b4,  p1, p2);
    if (sc & 4) cmul(a8,  b8,  p1, p2);
    if (sc & 8) cmul(a16, b16, p1, p2);

    // ---- final single store of out ----
#pragma unroll
    for (int i = 0; i < 2; i++) {
        float n1 = fmaf(cc, p1, -ss_ * p2);
        float n2 = fmaf(cc, p2,  ss_ * p1);
        p1 = n1; p2 = n2;
        int tt = 2 * sc + i;
        out[(t0 + tt) * H2 + h]      = rl1[i] + p1;
        out[(t0 + tt) * H2 + HH + h] = rl2[i] + p2;
    }
}

// ---------------------------------------------------------------------------
extern "C" void kernel_launch(void* const* d_in, const int* in_sizes, int n_in,
                              void* d_out, int out_size)
{
    const float* x     = (const float*)d_in[0];
    const float* lamda = (const float*)d_in[1];
    const float* theta = (const float*)d_in[2];
    const float* B1    = (const float*)d_in[3];
    const float* B2    = (const float*)d_in[4];
    float* out = (float*)d_out;

    static bool attr_set = false;
    if (!attr_set) {
        cudaFuncSetAttribute(rtrl_kernel,
                             cudaFuncAttributeMaxDynamicSharedMemorySize,
                             SMEM_BYTES);
        attr_set = true;
    }

    dim3 grid(NCHUNK, HH / 16);          // (16, 16) = 256 blocks, 2/SM
    rtrl_kernel<<<grid, NTHR, SMEM_BYTES>>>(x, B1, B2, lamda, theta, out);
}

// round 8
// speedup vs baseline: 1.1481x; 1.0109x over previous
#include <cuda_runtime.h>
#include <math.h>
#include <stdint.h>

// Problem dims
#define TT   512
#define DD   256
#define HH   256
#define H2   512

#define NCHUNK 16
#define LCH    32
#define NGRP   16                       // channel groups of 16
#define NTHR   256

// smem layout (floats)
#define STRA 260                        // padded k-major row stride
#define AS_OFF 0                        // as[32][260]  x tile (32 t rows)
#define BS_OFF (32 * STRA)              // bs[32][260]  16 B1 rows + 16 B2 rows
#define P_OFF  (BS_OFF + 32 * STRA)     // P[2][32][33] GEMM half partials
#define P_TS   33
#define P_HS   (32 * P_TS)
#define ES_OFF (P_OFF + 2 * P_HS)       // Es[16][32] subchunk ends
#define EP_OFF (ES_OFF + 16 * 32)       // epoch broadcast (1 int)
#define SMEM_FLOATS (EP_OFF + 1)
#define SMEM_BYTES (SMEM_FLOATS * 4)    // ~77 KB -> 2 blocks/SM

__device__ float g_E[NCHUNK * H2];      // per-chunk end states
__device__ int   g_flag[NCHUNK];        // monotonic publish counters (replay-safe)

#define FMA2(acc, a, b) \
    asm("fma.rn.f32x2 %0, %1, %2, %0;" : "+l"(acc) : "l"(a), "l"(b))

__device__ __forceinline__ float f32x2_sum(unsigned long long v) {
    float lo, hi;
    asm("mov.b64 {%0, %1}, %2;" : "=f"(lo), "=f"(hi) : "l"(v));
    return lo + hi;
}

__device__ __forceinline__ void cp16(float* smem_dst, const void* gsrc) {
    uint32_t sa = (uint32_t)__cvta_generic_to_shared(smem_dst);
    asm volatile("cp.async.cg.shared.global [%0], [%1], 16;" :: "r"(sa), "l"(gsrc));
}
#define CP_COMMIT() asm volatile("cp.async.commit_group;" ::: "memory")
#define CP_WAIT0()  asm volatile("cp.async.wait_group 0;" ::: "memory")
#define BARN(id, n) asm volatile("bar.sync %0, %1;" :: "r"(id), "r"(n) : "memory")

__device__ __forceinline__ void cmul(float a, float b, float& p1, float& p2) {
    float n1 = a * p1 - b * p2;
    float n2 = fmaf(a, p2, b * p1);
    p1 = n1; p2 = n2;
}

__device__ __forceinline__ void coeffs(const float* __restrict__ lamda,
                                       const float* __restrict__ theta,
                                       int h, float& c, float& s, float& gam)
{
    float e = expf(lamda[h]);
    float y = expf(-e);
    float z = expf(theta[h]);
    gam = sqrtf(fmaxf(1.0f - y * y, 0.0f));
    float cz, sz;
    sincosf(z, &sz, &cz);
    c = y * cz;
    s = y * sz;
}

// ---------------------------------------------------------------------------
// Single kernel, 256 blocks (16 chunks x 16 groups), 2 blocks/SM.
// Producer/consumer chunk flags instead of a global barrier:
//   staging -> GEMM -> scan -> publish g_E + flag[j]++ -> wait flags[i<j]
//   -> carry -> single store of out.
// ---------------------------------------------------------------------------
__global__ __launch_bounds__(NTHR, 2) void rtrl_kernel(
    const float* __restrict__ x,
    const float* __restrict__ B1,
    const float* __restrict__ B2,
    const float* __restrict__ lamda,
    const float* __restrict__ theta,
    float* __restrict__ out)
{
    extern __shared__ float sm[];
    float* as = sm + AS_OFF;
    float* bs = sm + BS_OFF;
    float* P  = sm + P_OFF;
    float* Es = sm + ES_OFF;
    int*   ep = (int*)(sm + EP_OFF);

    const int j   = blockIdx.x;          // chunk
    const int g   = blockIdx.y;          // 16-channel group
    const int t0  = j * LCH;
    const int ch0 = g * 16;
    const int tid = threadIdx.x;

    // ---- per-half staging: half hf loads k-quads [32*hf, 32*hf+32) ----
    const int hf = tid >> 7;             // 0/1
    const int r  = tid & 127;
    const float4* x4 = (const float4*)x;
#pragma unroll
    for (int i = 0; i < 8; i++) {        // as: 32 rows x 32 quads
        int idx = i * 128 + r;
        int row = idx >> 5;
        int qd  = 32 * hf + (idx & 31);
        cp16(&as[row * STRA + 4 * qd], &x4[(t0 + row) * 64 + qd]);
    }
#pragma unroll
    for (int i = 0; i < 8; i++) {        // bs: 32 rows (16 B1 + 16 B2) x 32 quads
        int idx = i * 128 + r;
        int row = idx >> 5;
        int qd  = 32 * hf + (idx & 31);
        const float4* Bsrc = (row < 16)
            ? (const float4*)(B1 + (ch0 + row) * DD)
            : (const float4*)(B2 + (ch0 + row - 16) * DD);
        cp16(&bs[row * STRA + 4 * qd], Bsrc + qd);
    }
    CP_COMMIT();

    // per-channel coefficients + rotation powers (overlap staging latency)
    const int ch = tid & 15;
    const int sc = tid >> 4;             // 0..15 subchunk of 2 steps
    const int h  = ch0 + ch;
    float cc, ss_, gam;
    coeffs(lamda, theta, h, cc, ss_, gam);
    float a2 = cc, b2 = ss_;    cmul(cc,  ss_, a2, b2);      // R^2
    float a4 = a2, b4 = b2;     cmul(a2,  b2,  a4, b4);      // R^4
    float a8 = a4, b8 = b4;     cmul(a4,  b4,  a8, b8);      // R^8
    float a16 = a8, b16 = b8;   cmul(a8,  b8,  a16, b16);    // R^16
    float a32 = a16, b32 = b16; cmul(a16, b16, a32, b32);    // R^32

    CP_WAIT0();
    BARN(1 + hf, 128);                   // half-local: own strip resident

    // ---- GEMM half: 32t x 32c x 128k, micro 4x2, f32x2 accumulators ----
    const int tsub = r >> 4;             // rows {tsub+8i}, i<4
    const int csub = r & 15;             // cols {csub+16i}, i<2

    unsigned long long acc[4][2];
#pragma unroll
    for (int i = 0; i < 4; i++) { acc[i][0] = 0ull; acc[i][1] = 0ull; }

#pragma unroll 8
    for (int kq = 32 * hf; kq < 32 * hf + 32; kq++) {
        int kf = kq * 4;
        ulonglong2 av[4], bv[2];
#pragma unroll
        for (int i = 0; i < 4; i++)
            av[i] = *(const ulonglong2*)&as[(tsub + 8 * i) * STRA + kf];
#pragma unroll
        for (int i = 0; i < 2; i++)
            bv[i] = *(const ulonglong2*)&bs[(csub + 16 * i) * STRA + kf];
#pragma unroll
        for (int i = 0; i < 4; i++)
#pragma unroll
            for (int jb = 0; jb < 2; jb++) {
                FMA2(acc[i][jb], av[i].x, bv[jb].x);
                FMA2(acc[i][jb], av[i].y, bv[jb].y);
            }
    }

#pragma unroll
    for (int i = 0; i < 4; i++)
#pragma unroll
        for (int jb = 0; jb < 2; jb++)
            P[hf * P_HS + (tsub + 8 * i) * P_TS + csub + 16 * jb] = f32x2_sum(acc[i][jb]);
    __syncthreads();

    // ---- parallel in-chunk scan: 16 subchunks of 2 steps, 16 channels ----
    float rl1[2], rl2[2];
    {
        float l1 = 0.f, l2 = 0.f;
#pragma unroll
        for (int i = 0; i < 2; i++) {
            int tt = 2 * sc + i;
            float b1v = P[tt * P_TS + ch]      + P[P_HS + tt * P_TS + ch];
            float b2v = P[tt * P_TS + 16 + ch] + P[P_HS + tt * P_TS + 16 + ch];
            float n1 = fmaf(cc, l1, fmaf(-ss_, l2, gam * b1v));
            float n2 = fmaf(cc, l2, fmaf( ss_, l1, gam * b2v));
            l1 = n1; l2 = n2;
            rl1[i] = l1; rl2[i] = l2;
        }
        Es[sc * 32 + ch]      = l1;
        Es[sc * 32 + 16 + ch] = l2;
    }
    __syncthreads();

    // subchunk carry: start(sc) = sum_{u<sc} R2^(sc-1-u) Es[u]
    {
        float p1 = 0.f, p2 = 0.f;
#pragma unroll
        for (int u = 0; u < 15; u++) {
            if (u < sc) {
                float e1 = Es[u * 32 + ch];
                float e2 = Es[u * 32 + 16 + ch];
                float n1 = fmaf(a2, p1, fmaf(-b2, p2, e1));
                float n2 = fmaf(a2, p2, fmaf( b2, p1, e2));
                p1 = n1; p2 = n2;
            }
        }
#pragma unroll
        for (int i = 0; i < 2; i++) {
            float n1 = fmaf(cc, p1, -ss_ * p2);
            float n2 = fmaf(cc, p2,  ss_ * p1);
            p1 = n1; p2 = n2;
            rl1[i] += p1; rl2[i] += p2;
        }
    }

    // ---- publish chunk end state + flag (monotonic, replay-safe) ----
    if (sc == 15) {
        g_E[j * H2 + h]      = rl1[1];
        g_E[j * H2 + HH + h] = rl2[1];
        __threadfence();                 // data visible before flag
    }
    __syncthreads();
    if (tid == 0) {
        int ticket = atomicAdd(&g_flag[j], 1);
        *ep = ticket >> 4;               // replay epoch (16 publishers/chunk)
    }
    __syncthreads();

    // ---- wait only on producer chunks i < j (threads 0..j-1 poll) ----
    if (j > 0) {
        int epoch = *ep;
        int target = (epoch + 1) << 4;   // 16*(epoch+1)
        if (tid < j) {
            while (*((volatile int*)&g_flag[tid]) < target) { }
            __threadfence();
        }
        __syncthreads();
    }

    // ---- cross-chunk carry (fully unrolled, predicated -> batched loads) ----
    float p1 = 0.f, p2 = 0.f;
#pragma unroll
    for (int i = 0; i < NCHUNK - 1; i++) {
        if (i < j) {
            float e1 = __ldcg(&g_E[i * H2 + h]);
            float e2 = __ldcg(&g_E[i * H2 + HH + h]);
            float n1 = fmaf(a32, p1, fmaf(-b32, p2, e1));
            float n2 = fmaf(a32, p2, fmaf( b32, p1, e2));
            p1 = n1; p2 = n2;
        }
    }
    // rotate carry to subchunk start: p *= R2^sc (binary exponent)
    if (sc & 1) cmul(a2,  b2,  p1, p2);
    if (sc & 2) cmul(a4,  b4,  p1, p2);
    if (sc & 4) cmul(a8,  b8,  p1, p2);
    if (sc & 8) cmul(a16, b16, p1, p2);

    // ---- final single store of out ----
#pragma unroll
    for (int i = 0; i < 2; i++) {
        float n1 = fmaf(cc, p1, -ss_ * p2);
        float n2 = fmaf(cc, p2,  ss_ * p1);
        p1 = n1; p2 = n2;
        int tt = 2 * sc + i;
        out[(t0 + tt) * H2 + h]      = rl1[i] + p1;
        out[(t0 + tt) * H2 + HH + h] = rl2[i] + p2;
    }
}

// ---------------------------------------------------------------------------
extern "C" void kernel_launch(void* const* d_in, const int* in_sizes, int n_in,
                              void* d_out, int out_size)
{
    const float* x     = (const float*)d_in[0];
    const float* lamda = (const float*)d_in[1];
    const float* theta = (const float*)d_in[2];
    const float* B1    = (const float*)d_in[3];
    const float* B2    = (const float*)d_in[4];
    float* out = (float*)d_out;

    static bool attr_set = false;
    if (!attr_set) {
        cudaFuncSetAttribute(rtrl_kernel,
                             cudaFuncAttributeMaxDynamicSharedMemorySize,
                             SMEM_BYTES);
        attr_set = true;
    }

    dim3 grid(NCHUNK, NGRP);             // (16, 16) = 256 blocks, 2/SM
    rtrl_kernel<<<grid, NTHR, SMEM_BYTES>>>(x, B1, B2, lamda, theta, out);
}

// round 9
// speedup vs baseline: 1.2917x; 1.1250x over previous
#include <cuda_runtime.h>
#include <math.h>
#include <stdint.h>

// Problem dims
#define TT   512
#define DD   256
#define HH   256
#define H2   512

#define NCHUNK 16
#define LCH    32
#define NBLOCKS 128

// smem layout (floats)
#define STRA 260                       // padded k-major row stride (16B-aligned rows)
#define AS_OFF 0                       // as[32][260]
#define BS_OFF (32 * STRA)             // bs[64][260]
#define SS_OFF (BS_OFF + 64 * STRA)    // Ss[32][68]
#define SS_STR 68
#define ES_OFF AS_OFF                  // Es[8][64] reuses as[] after GEMM
#define EP_OFF (SS_OFF + 32 * SS_STR)  // epoch broadcast (1 int)
#define SMEM_FLOATS (EP_OFF + 1)
#define SMEM_BYTES (SMEM_FLOATS * 4)

#define FLAG_STRIDE 32                 // 128 B between chunk flags

__device__ float g_E[NCHUNK * H2];     // per-chunk end states
__device__ int   g_flag[NCHUNK * FLAG_STRIDE];  // monotonic publish counters

#define FMA2(acc, a, b) \
    asm("fma.rn.f32x2 %0, %1, %2, %0;" : "+l"(acc) : "l"(a), "l"(b))

__device__ __forceinline__ float f32x2_sum(unsigned long long v) {
    float lo, hi;
    asm("mov.b64 {%0, %1}, %2;" : "=f"(lo), "=f"(hi) : "l"(v));
    return lo + hi;
}

__device__ __forceinline__ void cp16(float* smem_dst, const void* gsrc) {
    uint32_t sa = (uint32_t)__cvta_generic_to_shared(smem_dst);
    asm volatile("cp.async.cg.shared.global [%0], [%1], 16;" :: "r"(sa), "l"(gsrc));
}
#define CP_COMMIT() asm volatile("cp.async.commit_group;" ::: "memory")
#define CP_WAIT(n)  asm volatile("cp.async.wait_group %0;" :: "n"(n) : "memory")

__device__ __forceinline__ void cmul(float a, float b, float& p1, float& p2) {
    float n1 = a * p1 - b * p2;
    float n2 = fmaf(a, p2, b * p1);
    p1 = n1; p2 = n2;
}

__device__ __forceinline__ void coeffs(const float* __restrict__ lamda,
                                       const float* __restrict__ theta,
                                       int h, float& c, float& s, float& gam)
{
    float e = expf(lamda[h]);
    float y = expf(-e);
    float z = expf(theta[h]);
    gam = sqrtf(fmaxf(1.0f - y * y, 0.0f));
    float cz, sz;
    sincosf(z, &sz, &cz);
    c = y * cz;
    s = y * sz;
}

// ---------------------------------------------------------------------------
// Round-4 structure (best measured) with padded per-chunk flags tail.
// Block (j = chunk, g = 32-channel group), 256 threads, 1 block/SM.
// ---------------------------------------------------------------------------
__global__ __launch_bounds__(256, 1) void rtrl_kernel(
    const float* __restrict__ x,
    const float* __restrict__ B1,
    const float* __restrict__ B2,
    const float* __restrict__ lamda,
    const float* __restrict__ theta,
    float* __restrict__ out)
{
    extern __shared__ float sm[];
    float* as = sm + AS_OFF;
    float* bs = sm + BS_OFF;
    float* Ss = sm + SS_OFF;
    float* Es = sm + ES_OFF;
    int*   ep = (int*)(sm + EP_OFF);

    const int j   = blockIdx.x;        // chunk
    const int g   = blockIdx.y;        // channel group
    const int t0  = j * LCH;
    const int ch0 = g * 32;
    const int tid = threadIdx.x;
    const int ch  = tid & 31;
    const int sc  = tid >> 5;          // 0..7 (subchunk / t-slice)
    const int h   = ch0 + ch;

    float cc, ss_, gam;
    coeffs(lamda, theta, h, cc, ss_, gam);

    // ---- async staging: stage s covers k-strips {s, s+2} (strip = 16 quads) ----
    const float4* x4 = (const float4*)x;
#pragma unroll
    for (int s = 0; s < 2; s++) {
#pragma unroll
        for (int i = 0; i < 4; i++) {
            int idx = i * 256 + tid;
            int row = idx >> 5;                    // 0..31
            int qq  = idx & 31;
            int q   = ((qq >> 4) * 2 + s) * 16 + (qq & 15);
            cp16(&as[row * STRA + 4 * q], &x4[(t0 + row) * 64 + q]);
        }
#pragma unroll
        for (int i = 0; i < 8; i++) {
            int idx = i * 256 + tid;
            int row = idx >> 5;                    // 0..63
            int qq  = idx & 31;
            int q   = ((qq >> 4) * 2 + s) * 16 + (qq & 15);
            const float4* Bsrc = (row < 32)
                ? (const float4*)(B1 + (ch0 + row) * DD)
                : (const float4*)(B2 + (ch0 + row - 32) * DD);
            cp16(&bs[row * STRA + 4 * q], Bsrc + q);
        }
        CP_COMMIT();
    }

    // ---- GEMM: k-split halves, 4x4 strided micro-tile, f32x2 accumulators ----
    const int half = tid >> 7;         // 0/1 -> k quads [0,32) / [32,64)
    const int t7   = tid & 127;
    const int tsub = t7 >> 4;          // rows {tsub+8i}
    const int csub = t7 & 15;          // cols {csub+16i}
    const int kq0  = half * 32;

    unsigned long long acc[4][4];
#pragma unroll
    for (int i = 0; i < 4; i++)
#pragma unroll
        for (int jb = 0; jb < 4; jb++) acc[i][jb] = 0ull;

    CP_WAIT(1);
    __syncthreads();                   // stage A (strips 0,2) resident

#pragma unroll
    for (int ph = 0; ph < 2; ph++) {
        if (ph == 1) { CP_WAIT(0); __syncthreads(); }  // stage B resident
#pragma unroll 8
        for (int kq = ph * 16; kq < ph * 16 + 16; kq++) {
            int kf = (kq0 + kq) * 4;
            ulonglong2 av[4], bv[4];
#pragma unroll
            for (int i = 0; i < 4; i++)
                av[i] = *(const ulonglong2*)&as[(tsub + 8 * i) * STRA + kf];
#pragma unroll
            for (int i = 0; i < 4; i++)
                bv[i] = *(const ulonglong2*)&bs[(csub + 16 * i) * STRA + kf];
#pragma unroll
            for (int i = 0; i < 4; i++) {
#pragma unroll
                for (int jb = 0; jb < 4; jb++) {
                    FMA2(acc[i][jb], av[i].x, bv[jb].x);
                    FMA2(acc[i][jb], av[i].y, bv[jb].y);
                }
            }
        }
    }
    __syncthreads();

    // ---- reduce k-halves into Ss ----
    if (half) {
#pragma unroll
        for (int i = 0; i < 4; i++)
#pragma unroll
            for (int jb = 0; jb < 4; jb++)
                Ss[(tsub + 8 * i) * SS_STR + csub + 16 * jb] = f32x2_sum(acc[i][jb]);
    }
    __syncthreads();
    if (!half) {
#pragma unroll
        for (int i = 0; i < 4; i++)
#pragma unroll
            for (int jb = 0; jb < 4; jb++)
                Ss[(tsub + 8 * i) * SS_STR + csub + 16 * jb] += f32x2_sum(acc[i][jb]);
    }
    __syncthreads();

    // ---- parallel in-chunk scan: 8 subchunks of 4 steps, per channel ----
    float rl1[4], rl2[4];
    {
        float l1 = 0.f, l2 = 0.f;
#pragma unroll
        for (int i = 0; i < 4; i++) {
            int tt = 4 * sc + i;
            float b1 = Ss[tt * SS_STR + ch];
            float b2 = Ss[tt * SS_STR + 32 + ch];
            float n1 = fmaf(cc, l1, fmaf(-ss_, l2, gam * b1));
            float n2 = fmaf(cc, l2, fmaf( ss_, l1, gam * b2));
            l1 = n1; l2 = n2;
            rl1[i] = l1; rl2[i] = l2;
        }
        Es[sc * 64 + ch]      = l1;
        Es[sc * 64 + 32 + ch] = l2;
    }
    __syncthreads();

    // rotation powers
    float a4 = cc, b4 = ss_;
#pragma unroll
    for (int it = 0; it < 2; it++) { float na = a4*a4 - b4*b4, nb = 2.f*a4*b4; a4 = na; b4 = nb; }
    float a32 = a4, b32 = b4;
#pragma unroll
    for (int it = 0; it < 3; it++) { float na = a32*a32 - b32*b32, nb = 2.f*a32*b32; a32 = na; b32 = nb; }

    // compose subchunk carry and correct locals
    {
        float p1 = 0.f, p2 = 0.f;
#pragma unroll
        for (int u = 0; u < 7; u++) {
            if (u < sc) {
                float e1 = Es[u * 64 + ch];
                float e2 = Es[u * 64 + 32 + ch];
                float n1 = fmaf(a4, p1, fmaf(-b4, p2, e1));
                float n2 = fmaf(a4, p2, fmaf( b4, p1, e2));
                p1 = n1; p2 = n2;
            }
        }
#pragma unroll
        for (int i = 0; i < 4; i++) {
            float n1 = fmaf(cc, p1, -ss_ * p2);
            float n2 = fmaf(cc, p2,  ss_ * p1);
            p1 = n1; p2 = n2;
            rl1[i] += p1; rl2[i] += p2;
        }
    }

    // ---- publish chunk end state + padded flag (monotonic, replay-safe) ----
    if (sc == 7) {
        g_E[j * H2 + h]      = rl1[3];
        g_E[j * H2 + HH + h] = rl2[3];
        __threadfence();
    }
    __syncthreads();
    if (tid == 0) {
        int ticket = atomicAdd(&g_flag[j * FLAG_STRIDE], 1);
        *ep = ticket >> 3;             // 8 publishers per chunk
    }
    __syncthreads();

    // ---- wait only on producer chunks i < j (threads 0..j-1 poll) ----
    if (j > 0) {
        int target = ((*ep) + 1) << 3;
        if (tid < j) {
            while (*((volatile int*)&g_flag[tid * FLAG_STRIDE]) < target)
                __nanosleep(64);
            __threadfence();
        }
        __syncthreads();
    }

    // ---- cross-chunk carry + final single store of out ----
    float p1 = 0.f, p2 = 0.f;
#pragma unroll
    for (int i = 0; i < NCHUNK - 1; i++) {
        if (i < j) {
            float e1 = __ldcg(&g_E[i * H2 + h]);
            float e2 = __ldcg(&g_E[i * H2 + HH + h]);
            float n1 = fmaf(a32, p1, fmaf(-b32, p2, e1));
            float n2 = fmaf(a32, p2, fmaf( b32, p1, e2));
            p1 = n1; p2 = n2;
        }
    }
    // rotate carry to this thread's t-slice start: p *= R4^sc
    for (int it = 0; it < sc; it++) {
        float n1 = a4 * p1 - b4 * p2;
        float n2 = fmaf(a4, p2, b4 * p1);
        p1 = n1; p2 = n2;
    }
#pragma unroll
    for (int i = 0; i < 4; i++) {
        float n1 = fmaf(cc, p1, -ss_ * p2);
        float n2 = fmaf(cc, p2,  ss_ * p1);
        p1 = n1; p2 = n2;
        int tt = 4 * sc + i;
        out[(t0 + tt) * H2 + h]      = rl1[i] + p1;
        out[(t0 + tt) * H2 + HH + h] = rl2[i] + p2;
    }
}

// ---------------------------------------------------------------------------
extern "C" void kernel_launch(void* const* d_in, const int* in_sizes, int n_in,
                              void* d_out, int out_size)
{
    const float* x     = (const float*)d_in[0];
    const float* lamda = (const float*)d_in[1];
    const float* theta = (const float*)d_in[2];
    const float* B1    = (const float*)d_in[3];
    const float* B2    = (const float*)d_in[4];
    float* out = (float*)d_out;

    static bool attr_set = false;
    if (!attr_set) {
        cudaFuncSetAttribute(rtrl_kernel,
                             cudaFuncAttributeMaxDynamicSharedMemorySize,
                             SMEM_BYTES);
        attr_set = true;
    }

    dim3 grid(NCHUNK, HH / 32);        // (16, 8) = 128 blocks, all co-resident
    rtrl_kernel<<<grid, 256, SMEM_BYTES>>>(x, B1, B2, lamda, theta, out);
}